// round 15
// baseline (speedup 1.0000x reference)
#include <cuda_runtime.h>
#include <cuda_bf16.h>
#include <cstdint>

// Problem constants
#define Bb 2
#define Ss 2048
#define Dd 256
#define Hh 8
#define NR (Bb*Ss)

// Scratch: raw transposed operands + packed V + norms
__device__ __align__(16) float g_Qt[Bb*Dd*Ss];     // raw fp32, [b][k][s]
__device__ __align__(16) float g_Kt[Bb*Dd*Ss];     // raw fp32, [b][k][t]
__device__ __align__(16) uint32_t g_Vph[Bb*Dd*(Ss/2)], g_Vpl[Bb*Dd*(Ss/2)]; // bf16x2 pairs
__device__ float g_q2[NR];
__device__ float g_k2[NR];
// pre-split weights (tf32 hi/lo), [which][k][n]
__device__ __align__(16) float g_Wh[3*Dd*Dd], g_Wl[3*Dd*Dd];

// ===================== helpers =====================
__device__ __forceinline__ uint32_t f2tf32(float f) {
    uint32_t r;
    asm("cvt.rna.tf32.f32 %0, %1;" : "=r"(r) : "f"(f));
    return r;
}
__device__ __forceinline__ void split_tf32(float v, uint32_t& hi, uint32_t& lo) {
    hi = f2tf32(v);
    lo = f2tf32(v - __uint_as_float(hi));
}
__device__ __forceinline__ void mma_tf32(float* c, const uint32_t* a, const uint32_t* b) {
    asm volatile(
        "mma.sync.aligned.m16n8k8.row.col.f32.tf32.tf32.f32 "
        "{%0,%1,%2,%3}, {%4,%5,%6,%7}, {%8,%9}, {%0,%1,%2,%3};"
        : "+f"(c[0]), "+f"(c[1]), "+f"(c[2]), "+f"(c[3])
        : "r"(a[0]), "r"(a[1]), "r"(a[2]), "r"(a[3]), "r"(b[0]), "r"(b[1]));
}
__device__ __forceinline__ void mma_bf16(float* c, const uint32_t* a, const uint32_t* b) {
    asm volatile(
        "mma.sync.aligned.m16n8k16.row.col.f32.bf16.bf16.f32 "
        "{%0,%1,%2,%3}, {%4,%5,%6,%7}, {%8,%9}, {%0,%1,%2,%3};"
        : "+f"(c[0]), "+f"(c[1]), "+f"(c[2]), "+f"(c[3])
        : "r"(a[0]), "r"(a[1]), "r"(a[2]), "r"(a[3]), "r"(b[0]), "r"(b[1]));
}
__device__ __forceinline__ uint32_t pack_bf16x2(float lo_val, float hi_val) {
    __nv_bfloat16 l = __float2bfloat16(lo_val);
    __nv_bfloat16 h = __float2bfloat16(hi_val);
    return (uint32_t)__bfloat16_as_ushort(l) | ((uint32_t)__bfloat16_as_ushort(h) << 16);
}
// split pair (e0 -> low half, e1 -> high half) into bf16 hi + residual lo words
__device__ __forceinline__ void split2_bf16(float e0, float e1, uint32_t& hi, uint32_t& lo) {
    __nv_bfloat16 h0 = __float2bfloat16(e0);
    __nv_bfloat16 h1 = __float2bfloat16(e1);
    hi = (uint32_t)__bfloat16_as_ushort(h0) | ((uint32_t)__bfloat16_as_ushort(h1) << 16);
    lo = pack_bf16x2(e0 - __bfloat162float(h0), e1 - __bfloat162float(h1));
}
__device__ __forceinline__ uint32_t smem_to_u32(const void* smem_ptr) {
    uint32_t addr;
    asm("{ .reg .u64 tmp; cvta.to.shared.u64 tmp, %1; cvt.u32.u64 %0, tmp; }"
        : "=r"(addr) : "l"(smem_ptr));
    return addr;
}
#define CP_ASYNC16(dst, src) \
    asm volatile("cp.async.cg.shared.global [%0], [%1], 16;" :: "r"(dst), "l"(src))
#define CP_COMMIT() asm volatile("cp.async.commit_group;" ::: "memory")
#define CP_WAIT(n)  asm volatile("cp.async.wait_group %0;" :: "n"(n) : "memory")

// ---------------------------------------------------------------------------
// Kernel 0: pre-split weights into tf32 hi/lo.  grid (256, 3) block 256
// ---------------------------------------------------------------------------
__global__ __launch_bounds__(256) void wsplit_kernel(
    const float* __restrict__ Wq, const float* __restrict__ Wk,
    const float* __restrict__ Wv)
{
    const int which = blockIdx.y;
    const float* W = (which == 0) ? Wq : (which == 1) ? Wk : Wv;
    int i = blockIdx.x * 256 + threadIdx.x;
    float v = W[i];
    uint32_t hi, lo;
    split_tf32(v, hi, lo);
    g_Wh[which*Dd*Dd + i] = __uint_as_float(hi);
    g_Wl[which*Dd*Dd + i] = __uint_as_float(lo);
}

// ---------------------------------------------------------------------------
// Kernel 0b: zero only LEADER-head output slices (atomicAdd targets).
// Duplicate heads are fully overwritten by bcast_kernel stores.
// grid: ((Ss*Dd)/1024, Hh, Bb)  block: 256
// ---------------------------------------------------------------------------
__global__ __launch_bounds__(256) void zero_kernel(
    const float* __restrict__ gamma, float* __restrict__ out)
{
    const int h = blockIdx.y, b = blockIdx.z;
    const float gh = gamma[h];
    for (int h2 = 0; h2 < h; h2++)
        if (gamma[h2] == gh) return;           // not a leader: no zeroing needed
    size_t idx = ((size_t)blockIdx.x * 256 + threadIdx.x) * 4;
    *(float4*)&out[((size_t)(b*Hh + h)*Ss)*Dd + idx] = make_float4(0.f, 0.f, 0.f, 0.f);
}

// ---------------------------------------------------------------------------
// Kernel 1: split-tf32 MMA projections; A raw + register split, B pre-split.
// Block tile 128m x 64n, warp tile 32x32 (4x2 warps).  [R14-proven]
// grid: (NR/128, Dd/64, 3)  block: 256
// ---------------------------------------------------------------------------
#define MSTR 36     // A raw [m][k] stride (floats): bank = 4r+cc
#define BSTR 72     // B [k][n] stride: bank = 8cc+r
#define PROJ_SMEM (18432*4)   // 73728 B

__global__ __launch_bounds__(256, 2) void proj_mma_kernel(
    const float* __restrict__ p, const float* __restrict__ e)
{
    const int which = blockIdx.z;
    const float* src = (which == 2) ? e : p;
    const float* Whg = g_Wh + (size_t)which*Dd*Dd;
    const float* Wlg = g_Wl + (size_t)which*Dd*Dd;

    const int row0 = blockIdx.x * 128;
    const int col0 = blockIdx.y * 64;
    const int b    = row0 >> 11;
    const int s_in = row0 & (Ss - 1);

    extern __shared__ float psm[];
    const uint32_t smb = smem_to_u32(psm);

    const int tid = threadIdx.x, lane = tid & 31, wid = tid >> 5;
    const int wm = wid & 3, wn = wid >> 2;
    const int r = lane >> 2, cc = lane & 3;

    float C[2][4][4] = {};

    #define P_ISSUE(sl, buf) do { \
        const int k0i = (sl)*32; \
        for (int i = tid; i < 1024; i += 256) { \
            int row = i >> 3, ch = i & 7; \
            CP_ASYNC16(smb + (uint32_t)(((buf)*4608 + row*MSTR + ch*4))*4u, \
                       (const void*)(src + (size_t)(row0 + row)*Dd + k0i + ch*4)); \
        } \
        for (int i = tid; i < 512; i += 256) { \
            int row = i >> 4, ch = i & 15; \
            size_t go = (size_t)(k0i + row)*Dd + col0 + ch*4; \
            CP_ASYNC16(smb + (uint32_t)((9216 + (buf)*2304 + row*BSTR + ch*4))*4u, \
                       (const void*)(Whg + go)); \
            CP_ASYNC16(smb + (uint32_t)((13824 + (buf)*2304 + row*BSTR + ch*4))*4u, \
                       (const void*)(Wlg + go)); \
        } \
    } while (0)

    P_ISSUE(0, 0); CP_COMMIT();

    for (int sl = 0; sl < 8; sl++) {
        if (sl + 1 < 8) { P_ISSUE(sl + 1, (sl + 1) & 1); CP_COMMIT(); CP_WAIT(1); }
        else            { CP_WAIT(0); }
        __syncthreads();

        const float* Ab = psm + (sl & 1)*4608;
        const uint32_t* uBh = (const uint32_t*)(psm + 9216  + (sl & 1)*2304);
        const uint32_t* uBl = (const uint32_t*)(psm + 13824 + (sl & 1)*2304);

        #pragma unroll
        for (int ks = 0; ks < 4; ks++) {
            const int kc = ks*8 + cc;
            uint32_t ah[2][4], al[2][4];
            #pragma unroll
            for (int mf = 0; mf < 2; mf++) {
                int m0 = wm*32 + mf*16 + r;
                split_tf32(Ab[m0*MSTR + kc],         ah[mf][0], al[mf][0]);
                split_tf32(Ab[(m0+8)*MSTR + kc],     ah[mf][1], al[mf][1]);
                split_tf32(Ab[m0*MSTR + kc + 4],     ah[mf][2], al[mf][2]);
                split_tf32(Ab[(m0+8)*MSTR + kc + 4], ah[mf][3], al[mf][3]);
            }
            uint32_t bh[4][2], bl[4][2];
            #pragma unroll
            for (int nf = 0; nf < 4; nf++) {
                int ncol = wn*32 + nf*8 + r;
                bh[nf][0] = uBh[kc*BSTR + ncol];
                bh[nf][1] = uBh[(kc+4)*BSTR + ncol];
                bl[nf][0] = uBl[kc*BSTR + ncol];
                bl[nf][1] = uBl[(kc+4)*BSTR + ncol];
            }
            #pragma unroll
            for (int mf = 0; mf < 2; mf++)
                #pragma unroll
                for (int nf = 0; nf < 4; nf++) {
                    mma_tf32(C[mf][nf], ah[mf], bh[nf]);
                    mma_tf32(C[mf][nf], ah[mf], bl[nf]);
                    mma_tf32(C[mf][nf], al[mf], bh[nf]);
                }
        }
        __syncthreads();
    }

    // ---- epilogue: bounce through smem, write raw transposed + norms ----
    float* Ts = psm;                 // 128 x 65 fp32
    #pragma unroll
    for (int mf = 0; mf < 2; mf++) {
        int s = wm*32 + mf*16 + r;
        #pragma unroll
        for (int nf = 0; nf < 4; nf++) {
            int n = wn*32 + nf*8 + 2*cc;
            Ts[s*65 + n]         = C[mf][nf][0];
            Ts[s*65 + n + 1]     = C[mf][nf][1];
            Ts[(s+8)*65 + n]     = C[mf][nf][2];
            Ts[(s+8)*65 + n + 1] = C[mf][nf][3];
        }
    }
    __syncthreads();

    if (which < 2) {
        float* dst = (which == 0) ? g_Qt : g_Kt;
        float* nrm = (which == 0) ? g_q2 : g_k2;
        const int sc = tid & 127;
        const int kc0 = tid >> 7;
        float psum = 0.0f;
        #pragma unroll 8
        for (int i = 0; i < 32; i++) {
            int kc = kc0 + 2*i;
            float v = Ts[sc*65 + kc];
            psum += v * v;
            dst[((size_t)(b*Dd + col0 + kc))*Ss + s_in + sc] = v;
        }
        atomicAdd(&nrm[row0 + sc], psum);
    } else {
        for (int l = tid; l < 64*64; l += 256) {
            int kc = l >> 6, pr = l & 63;
            float v0 = Ts[(2*pr)*65 + kc];
            float v1 = Ts[(2*pr + 1)*65 + kc];
            uint32_t hi, lo;
            split2_bf16(v0, v1, hi, lo);
            size_t oi = ((size_t)(b*Dd + col0 + kc))*(Ss/2) + (s_in >> 1) + pr;
            g_Vph[oi] = hi;
            g_Vpl[oi] = lo;
        }
    }
}

// ---------------------------------------------------------------------------
// Kernel 2 (fused attn) [R14-proven]: Phase A: S = QK^T via split-bf16
// m16n8k16, cp.async raw Q/K double-buffered, register bf16 split ->
// P = exp(coef*d2) split-bf16 in smem. Phase B: per 64-wide d-chunk, stage
// both V tiles, 96 MMAs, atomicAdd to leader head.
// grid: (16, 16, Bb*Hh)  block: 256
// ---------------------------------------------------------------------------
#define QSTR 136    // Q raw [k][s] stride
#define KSTR 72     // K raw [k][t] stride
#define PSTR 36
#define VSTR 36
#define U_OFF 18432
#define FUSED_SMEM ((18432 + 9216)*4)   // 110592 B

__global__ __launch_bounds__(256, 2) void fused_attn_kernel(
    const float* __restrict__ gamma, float* __restrict__ out)
{
    const int si = blockIdx.x;
    const int chunk = blockIdx.y;
    if (chunk > si) return;
    const int z = blockIdx.z;
    const int b = z >> 3, h = z & 7;
    const float gh = gamma[h];
    for (int h2 = 0; h2 < h; h2++)
        if (gamma[h2] == gh) return;           // leader only
    const float coef = -1.0f / (-2.0f * gh + 1e-6f);

    const int s0 = si * 128;
    const int t0a = chunk * 128;
    const int t0b = t0a + 64;

    extern __shared__ uint32_t smu[];
    uint32_t* Ph[2] = { smu,        smu + 9216 };
    uint32_t* Pl[2] = { smu + 4608, smu + 13824 };
    uint32_t* U = smu + U_OFF;
    const uint32_t ub = smem_to_u32((const void*)U);

    const int tid = threadIdx.x, lane = tid & 31, wid = tid >> 5;
    const int wm = wid & 3, wn = wid >> 2;
    const int r = lane >> 2, cc = lane & 3;

    const float* Qg = g_Qt + (size_t)b*Dd*Ss;
    const float* Kg = g_Kt + (size_t)b*Dd*Ss;

    // ---------------- Phase A: 16 slabs of k16, split-bf16 MMAs ----------
    float C0[2][4][4] = {}, C1[2][4][4] = {};

    #define QK_ISSUE(sl, buf) do { \
        const int k0i = (sl)*16; \
        for (int i = tid; i < 512; i += 256) { \
            int row = i >> 5, ch = i & 31; \
            CP_ASYNC16(ub + (uint32_t)((buf)*2176 + row*QSTR + ch*4)*4u, \
                       (const void*)(Qg + (size_t)(k0i + row)*Ss + s0 + ch*4)); \
        } \
        { int row = tid >> 4, ch = tid & 15; \
          CP_ASYNC16(ub + (uint32_t)(4352 + (buf)*2304 + row*KSTR + ch*4)*4u, \
                     (const void*)(Kg + (size_t)(k0i + row)*Ss + t0a + ch*4)); \
          CP_ASYNC16(ub + (uint32_t)(4352 + (buf)*2304 + 1152 + row*KSTR + ch*4)*4u, \
                     (const void*)(Kg + (size_t)(k0i + row)*Ss + t0b + ch*4)); } \
    } while (0)

    QK_ISSUE(0, 0); CP_COMMIT();

    for (int sl = 0; sl < 16; sl++) {
        if (sl + 1 < 16) { QK_ISSUE(sl + 1, (sl + 1) & 1); CP_COMMIT(); CP_WAIT(1); }
        else             { CP_WAIT(0); }
        __syncthreads();

        const float* Qb = (const float*)(U + (sl & 1)*2176);
        const float* Kb0 = (const float*)(U + 4352 + (sl & 1)*2304);
        const float* Kb1 = Kb0 + 1152;

        uint32_t ah[2][4], al[2][4];
        #pragma unroll
        for (int mf = 0; mf < 2; mf++) {
            int m0 = wm*32 + mf*16 + r;
            split2_bf16(Qb[(2*cc)*QSTR + m0],       Qb[(2*cc+1)*QSTR + m0],
                        ah[mf][0], al[mf][0]);
            split2_bf16(Qb[(2*cc)*QSTR + m0 + 8],   Qb[(2*cc+1)*QSTR + m0 + 8],
                        ah[mf][1], al[mf][1]);
            split2_bf16(Qb[(2*cc+8)*QSTR + m0],     Qb[(2*cc+9)*QSTR + m0],
                        ah[mf][2], al[mf][2]);
            split2_bf16(Qb[(2*cc+8)*QSTR + m0 + 8], Qb[(2*cc+9)*QSTR + m0 + 8],
                        ah[mf][3], al[mf][3]);
        }
        {   // tile 0
            uint32_t bh[4][2], bl[4][2];
            #pragma unroll
            for (int nf = 0; nf < 4; nf++) {
                int ncol = wn*32 + nf*8 + r;
                split2_bf16(Kb0[(2*cc)*KSTR + ncol],   Kb0[(2*cc+1)*KSTR + ncol],
                            bh[nf][0], bl[nf][0]);
                split2_bf16(Kb0[(2*cc+8)*KSTR + ncol], Kb0[(2*cc+9)*KSTR + ncol],
                            bh[nf][1], bl[nf][1]);
            }
            #pragma unroll
            for (int mf = 0; mf < 2; mf++)
                #pragma unroll
                for (int nf = 0; nf < 4; nf++) {
                    mma_bf16(C0[mf][nf], ah[mf], bh[nf]);
                    mma_bf16(C0[mf][nf], ah[mf], bl[nf]);
                    mma_bf16(C0[mf][nf], al[mf], bh[nf]);
                }
        }
        {   // tile 1
            uint32_t bh[4][2], bl[4][2];
            #pragma unroll
            for (int nf = 0; nf < 4; nf++) {
                int ncol = wn*32 + nf*8 + r;
                split2_bf16(Kb1[(2*cc)*KSTR + ncol],   Kb1[(2*cc+1)*KSTR + ncol],
                            bh[nf][0], bl[nf][0]);
                split2_bf16(Kb1[(2*cc+8)*KSTR + ncol], Kb1[(2*cc+9)*KSTR + ncol],
                            bh[nf][1], bl[nf][1]);
            }
            #pragma unroll
            for (int mf = 0; mf < 2; mf++)
                #pragma unroll
                for (int nf = 0; nf < 4; nf++) {
                    mma_bf16(C1[mf][nf], ah[mf], bh[nf]);
                    mma_bf16(C1[mf][nf], ah[mf], bl[nf]);
                    mma_bf16(C1[mf][nf], al[mf], bh[nf]);
                }
        }
        __syncthreads();
    }

    // ---------------- Epilogue A: P = exp(coef * d2), split bf16 --------
    #pragma unroll
    for (int tl = 0; tl < 2; tl++) {
        const int t0 = tl ? t0b : t0a;
        float (*C)[4][4] = tl ? C1 : C0;
        #pragma unroll
        for (int mf = 0; mf < 2; mf++) {
            int sl2 = wm*32 + mf*16 + r;
            int sg = s0 + sl2;
            float q2a = g_q2[b*Ss + sg];
            float q2c = g_q2[b*Ss + sg + 8];
            #pragma unroll
            for (int nf = 0; nf < 4; nf++) {
                int tg = t0 + wn*32 + nf*8 + 2*cc;
                float k2a = g_k2[b*Ss + tg];
                float k2b = g_k2[b*Ss + tg + 1];
                float p00 = (tg     > sg) ? 0.0f : __expf(coef * fmaxf(q2a + k2a - 2.0f*C[mf][nf][0], 0.0f));
                float p01 = (tg + 1 > sg) ? 0.0f : __expf(coef * fmaxf(q2a + k2b - 2.0f*C[mf][nf][1], 0.0f));
                float p10 = (tg     > sg + 8) ? 0.0f : __expf(coef * fmaxf(q2c + k2a - 2.0f*C[mf][nf][2], 0.0f));
                float p11 = (tg + 1 > sg + 8) ? 0.0f : __expf(coef * fmaxf(q2c + k2b - 2.0f*C[mf][nf][3], 0.0f));
                int pidx = wn*16 + nf*4 + cc;
                uint32_t hi0, lo0, hi1, lo1;
                split2_bf16(p00, p01, hi0, lo0);
                split2_bf16(p10, p11, hi1, lo1);
                Ph[tl][sl2*PSTR + pidx]     = hi0;
                Ph[tl][(sl2+8)*PSTR + pidx] = hi1;
                Pl[tl][sl2*PSTR + pidx]     = lo0;
                Pl[tl][(sl2+8)*PSTR + pidx] = lo1;
            }
        }
    }
    __syncthreads();

    // ---------------- Phase B: OUT += P @ V^T per d-chunk ----------------
    uint32_t* Vh[2] = { U,        U + 4608 };
    uint32_t* Vl[2] = { U + 2304, U + 6912 };
    float* o = out + ((size_t)(b*Hh + h)*Ss)*Dd;

    for (int dch = 0; dch < 4; dch++) {
        for (int l = tid; l < 512; l += 256) {
            int d = l >> 3, c = l & 7;
            size_t gia = ((size_t)(b*Dd + dch*64 + d))*(Ss/2) + t0a/2 + c*4;
            size_t gib = ((size_t)(b*Dd + dch*64 + d))*(Ss/2) + t0b/2 + c*4;
            *(uint4*)&Vh[0][d*VSTR + c*4] = *(const uint4*)(g_Vph + gia);
            *(uint4*)&Vl[0][d*VSTR + c*4] = *(const uint4*)(g_Vpl + gia);
            *(uint4*)&Vh[1][d*VSTR + c*4] = *(const uint4*)(g_Vph + gib);
            *(uint4*)&Vl[1][d*VSTR + c*4] = *(const uint4*)(g_Vpl + gib);
        }
        __syncthreads();

        float C[2][4][4] = {};
        #pragma unroll
        for (int tl = 0; tl < 2; tl++) {
            #pragma unroll
            for (int ks = 0; ks < 4; ks++) {
                const int pc = ks*8 + cc;
                uint32_t ah[2][4], al[2][4];
                #pragma unroll
                for (int mf = 0; mf < 2; mf++) {
                    int srow = wm*32 + mf*16 + r;
                    ah[mf][0] = Ph[tl][srow*PSTR + pc];
                    ah[mf][1] = Ph[tl][(srow+8)*PSTR + pc];
                    ah[mf][2] = Ph[tl][srow*PSTR + pc + 4];
                    ah[mf][3] = Ph[tl][(srow+8)*PSTR + pc + 4];
                    al[mf][0] = Pl[tl][srow*PSTR + pc];
                    al[mf][1] = Pl[tl][(srow+8)*PSTR + pc];
                    al[mf][2] = Pl[tl][srow*PSTR + pc + 4];
                    al[mf][3] = Pl[tl][(srow+8)*PSTR + pc + 4];
                }
                uint32_t bh[4][2], bl[4][2];
                #pragma unroll
                for (int nf = 0; nf < 4; nf++) {
                    int dcol = wn*32 + nf*8 + r;
                    bh[nf][0] = Vh[tl][dcol*VSTR + pc];
                    bh[nf][1] = Vh[tl][dcol*VSTR + pc + 4];
                    bl[nf][0] = Vl[tl][dcol*VSTR + pc];
                    bl[nf][1] = Vl[tl][dcol*VSTR + pc + 4];
                }
                #pragma unroll
                for (int mf = 0; mf < 2; mf++)
                    #pragma unroll
                    for (int nf = 0; nf < 4; nf++) {
                        mma_bf16(C[mf][nf], ah[mf], bh[nf]);
                        mma_bf16(C[mf][nf], ah[mf], bl[nf]);
                        mma_bf16(C[mf][nf], al[mf], bh[nf]);
                    }
            }
        }
        #pragma unroll
        for (int mf = 0; mf < 2; mf++) {
            int s = s0 + wm*32 + mf*16 + r;
            #pragma unroll
            for (int nf = 0; nf < 4; nf++) {
                int d = dch*64 + wn*32 + nf*8 + 2*cc;
                atomicAdd(&o[(size_t)s*Dd + d],         C[mf][nf][0]);
                atomicAdd(&o[(size_t)s*Dd + d + 1],     C[mf][nf][1]);
                atomicAdd(&o[(size_t)(s+8)*Dd + d],     C[mf][nf][2]);
                atomicAdd(&o[(size_t)(s+8)*Dd + d + 1], C[mf][nf][3]);
            }
        }
        if (dch < 3) __syncthreads();   // last iter: nothing reads smem after
    }
}

// ---------------------------------------------------------------------------
// Kernel 3: broadcast v2 — leader reads its value once, stores to every
// duplicate-gamma head.  grid: ((Ss*Dd)/1024, Hh, Bb)  block: 256
// ---------------------------------------------------------------------------
__global__ __launch_bounds__(256) void bcast_kernel(
    const float* __restrict__ gamma, float* __restrict__ out)
{
    const int h = blockIdx.y, b = blockIdx.z;
    const float gh = gamma[h];
    for (int h2 = 0; h2 < h; h2++)
        if (gamma[h2] == gh) return;           // only leaders broadcast

    size_t idx = ((size_t)blockIdx.x * 256 + threadIdx.x) * 4;
    const float4 v = *(const float4*)&out[((size_t)(b*Hh + h)*Ss)*Dd + idx];
    for (int h2 = h + 1; h2 < Hh; h2++) {
        if (gamma[h2] != gh) continue;
        *(float4*)&out[((size_t)(b*Hh + h2)*Ss)*Dd + idx] = v;
    }
}

// ---------------------------------------------------------------------------
extern "C" void kernel_launch(void* const* d_in, const int* in_sizes, int n_in,
                              void* d_out, int out_size)
{
    // metadata order: x, e, p, W_q, W_k, W_v, gamma
    const float* e     = (const float*)d_in[1];
    const float* p     = (const float*)d_in[2];
    const float* Wq    = (const float*)d_in[3];
    const float* Wk    = (const float*)d_in[4];
    const float* Wv    = (const float*)d_in[5];
    const float* gamma = (const float*)d_in[6];
    float* out = (float*)d_out;

    static bool init_done = false;
    static void *q2p = nullptr, *k2p = nullptr;
    if (!init_done) {
        cudaFuncSetAttribute(proj_mma_kernel,
                             cudaFuncAttributeMaxDynamicSharedMemorySize, PROJ_SMEM);
        cudaFuncSetAttribute(fused_attn_kernel,
                             cudaFuncAttributeMaxDynamicSharedMemorySize, FUSED_SMEM);
        cudaGetSymbolAddress(&q2p, g_q2);
        cudaGetSymbolAddress(&k2p, g_k2);
        init_done = true;
    }

    cudaMemsetAsync(q2p, 0, NR * sizeof(float));
    cudaMemsetAsync(k2p, 0, NR * sizeof(float));

    dim3 gz((Ss*Dd)/1024, Hh, Bb);
    zero_kernel<<<gz, 256>>>(gamma, out);

    dim3 gw(Dd*Dd/256, 3);
    wsplit_kernel<<<gw, 256>>>(Wq, Wk, Wv);

    dim3 gproj(NR/128, Dd/64, 3);
    proj_mma_kernel<<<gproj, 256, PROJ_SMEM>>>(p, e);

    dim3 gf(16, 16, Bb*Hh);
    fused_attn_kernel<<<gf, 256, FUSED_SMEM>>>(gamma, out);

    dim3 gb((Ss*Dd)/1024, Hh, Bb);
    bcast_kernel<<<gb, 256>>>(gamma, out);
}

// round 16
// speedup vs baseline: 1.1777x; 1.1777x over previous
#include <cuda_runtime.h>
#include <cuda_bf16.h>
#include <cstdint>

// Problem constants
#define Bb 2
#define Ss 2048
#define Dd 256
#define Hh 8
#define NR (Bb*Ss)

// Scratch: pre-split packed operands + norms
// Q/K: bf16x2 pairs over adjacent k, layout [b][k/2][s]
__device__ __align__(16) uint32_t g_Qph[Bb*(Dd/2)*Ss], g_Qpl[Bb*(Dd/2)*Ss];
__device__ __align__(16) uint32_t g_Kph[Bb*(Dd/2)*Ss], g_Kpl[Bb*(Dd/2)*Ss];
// V: bf16x2 pairs over adjacent t, layout [b][d][t/2]
__device__ __align__(16) uint32_t g_Vph[Bb*Dd*(Ss/2)], g_Vpl[Bb*Dd*(Ss/2)];
__device__ float g_q2[NR];
__device__ float g_k2[NR];
// pre-split weights (tf32 hi/lo), [which][k][n]
__device__ __align__(16) float g_Wh[3*Dd*Dd], g_Wl[3*Dd*Dd];

// ===================== helpers =====================
__device__ __forceinline__ uint32_t f2tf32(float f) {
    uint32_t r;
    asm("cvt.rna.tf32.f32 %0, %1;" : "=r"(r) : "f"(f));
    return r;
}
__device__ __forceinline__ void split_tf32(float v, uint32_t& hi, uint32_t& lo) {
    hi = f2tf32(v);
    lo = f2tf32(v - __uint_as_float(hi));
}
__device__ __forceinline__ void mma_tf32(float* c, const uint32_t* a, const uint32_t* b) {
    asm volatile(
        "mma.sync.aligned.m16n8k8.row.col.f32.tf32.tf32.f32 "
        "{%0,%1,%2,%3}, {%4,%5,%6,%7}, {%8,%9}, {%0,%1,%2,%3};"
        : "+f"(c[0]), "+f"(c[1]), "+f"(c[2]), "+f"(c[3])
        : "r"(a[0]), "r"(a[1]), "r"(a[2]), "r"(a[3]), "r"(b[0]), "r"(b[1]));
}
__device__ __forceinline__ void mma_bf16(float* c, const uint32_t* a, const uint32_t* b) {
    asm volatile(
        "mma.sync.aligned.m16n8k16.row.col.f32.bf16.bf16.f32 "
        "{%0,%1,%2,%3}, {%4,%5,%6,%7}, {%8,%9}, {%0,%1,%2,%3};"
        : "+f"(c[0]), "+f"(c[1]), "+f"(c[2]), "+f"(c[3])
        : "r"(a[0]), "r"(a[1]), "r"(a[2]), "r"(a[3]), "r"(b[0]), "r"(b[1]));
}
__device__ __forceinline__ uint32_t pack_bf16x2(float lo_val, float hi_val) {
    __nv_bfloat16 l = __float2bfloat16(lo_val);
    __nv_bfloat16 h = __float2bfloat16(hi_val);
    return (uint32_t)__bfloat16_as_ushort(l) | ((uint32_t)__bfloat16_as_ushort(h) << 16);
}
// split pair (e0 -> low half, e1 -> high half) into bf16 hi + residual lo words
__device__ __forceinline__ void split2_bf16(float e0, float e1, uint32_t& hi, uint32_t& lo) {
    __nv_bfloat16 h0 = __float2bfloat16(e0);
    __nv_bfloat16 h1 = __float2bfloat16(e1);
    hi = (uint32_t)__bfloat16_as_ushort(h0) | ((uint32_t)__bfloat16_as_ushort(h1) << 16);
    lo = pack_bf16x2(e0 - __bfloat162float(h0), e1 - __bfloat162float(h1));
}
__device__ __forceinline__ uint32_t smem_to_u32(const void* smem_ptr) {
    uint32_t addr;
    asm("{ .reg .u64 tmp; cvta.to.shared.u64 tmp, %1; cvt.u32.u64 %0, tmp; }"
        : "=r"(addr) : "l"(smem_ptr));
    return addr;
}
#define CP_ASYNC16(dst, src) \
    asm volatile("cp.async.cg.shared.global [%0], [%1], 16;" :: "r"(dst), "l"(src))
#define CP_COMMIT() asm volatile("cp.async.commit_group;" ::: "memory")
#define CP_WAIT(n)  asm volatile("cp.async.wait_group %0;" :: "n"(n) : "memory")

// ---------------------------------------------------------------------------
// Kernel 0: pre-split weights into tf32 hi/lo.  grid (256, 3) block 256
// ---------------------------------------------------------------------------
__global__ __launch_bounds__(256) void wsplit_kernel(
    const float* __restrict__ Wq, const float* __restrict__ Wk,
    const float* __restrict__ Wv)
{
    const int which = blockIdx.y;
    const float* W = (which == 0) ? Wq : (which == 1) ? Wk : Wv;
    int i = blockIdx.x * 256 + threadIdx.x;
    float v = W[i];
    uint32_t hi, lo;
    split_tf32(v, hi, lo);
    g_Wh[which*Dd*Dd + i] = __uint_as_float(hi);
    g_Wl[which*Dd*Dd + i] = __uint_as_float(lo);
}

// ---------------------------------------------------------------------------
// Kernel 0b: zero only LEADER-head output slices (atomicAdd targets).
// grid: ((Ss*Dd)/1024, Hh, Bb)  block: 256
// ---------------------------------------------------------------------------
__global__ __launch_bounds__(256) void zero_kernel(
    const float* __restrict__ gamma, float* __restrict__ out)
{
    const int h = blockIdx.y, b = blockIdx.z;
    const float gh = gamma[h];
    for (int h2 = 0; h2 < h; h2++)
        if (gamma[h2] == gh) return;           // not a leader
    size_t idx = ((size_t)blockIdx.x * 256 + threadIdx.x) * 4;
    *(float4*)&out[((size_t)(b*Hh + h)*Ss)*Dd + idx] = make_float4(0.f, 0.f, 0.f, 0.f);
}

// ---------------------------------------------------------------------------
// Kernel 1: split-tf32 MMA projections; A raw + register split, B pre-split.
// Epilogue writes PRE-SPLIT packed bf16x2 operands for the fused kernel.
// grid: (NR/128, Dd/64, 3)  block: 256
// ---------------------------------------------------------------------------
#define MSTR 36     // A raw [m][k] stride (floats): bank = 4r+cc
#define BSTR 72     // B [k][n] stride: bank = 8cc+r
#define PROJ_SMEM (18432*4)   // 73728 B

__global__ __launch_bounds__(256, 2) void proj_mma_kernel(
    const float* __restrict__ p, const float* __restrict__ e)
{
    const int which = blockIdx.z;
    const float* src = (which == 2) ? e : p;
    const float* Whg = g_Wh + (size_t)which*Dd*Dd;
    const float* Wlg = g_Wl + (size_t)which*Dd*Dd;

    const int row0 = blockIdx.x * 128;
    const int col0 = blockIdx.y * 64;
    const int b    = row0 >> 11;
    const int s_in = row0 & (Ss - 1);

    extern __shared__ float psm[];
    const uint32_t smb = smem_to_u32(psm);

    const int tid = threadIdx.x, lane = tid & 31, wid = tid >> 5;
    const int wm = wid & 3, wn = wid >> 2;
    const int r = lane >> 2, cc = lane & 3;

    float C[2][4][4] = {};

    #define P_ISSUE(sl, buf) do { \
        const int k0i = (sl)*32; \
        for (int i = tid; i < 1024; i += 256) { \
            int row = i >> 3, ch = i & 7; \
            CP_ASYNC16(smb + (uint32_t)(((buf)*4608 + row*MSTR + ch*4))*4u, \
                       (const void*)(src + (size_t)(row0 + row)*Dd + k0i + ch*4)); \
        } \
        for (int i = tid; i < 512; i += 256) { \
            int row = i >> 4, ch = i & 15; \
            size_t go = (size_t)(k0i + row)*Dd + col0 + ch*4; \
            CP_ASYNC16(smb + (uint32_t)((9216 + (buf)*2304 + row*BSTR + ch*4))*4u, \
                       (const void*)(Whg + go)); \
            CP_ASYNC16(smb + (uint32_t)((13824 + (buf)*2304 + row*BSTR + ch*4))*4u, \
                       (const void*)(Wlg + go)); \
        } \
    } while (0)

    P_ISSUE(0, 0); CP_COMMIT();

    for (int sl = 0; sl < 8; sl++) {
        if (sl + 1 < 8) { P_ISSUE(sl + 1, (sl + 1) & 1); CP_COMMIT(); CP_WAIT(1); }
        else            { CP_WAIT(0); }
        __syncthreads();

        const float* Ab = psm + (sl & 1)*4608;
        const uint32_t* uBh = (const uint32_t*)(psm + 9216  + (sl & 1)*2304);
        const uint32_t* uBl = (const uint32_t*)(psm + 13824 + (sl & 1)*2304);

        #pragma unroll
        for (int ks = 0; ks < 4; ks++) {
            const int kc = ks*8 + cc;
            uint32_t ah[2][4], al[2][4];
            #pragma unroll
            for (int mf = 0; mf < 2; mf++) {
                int m0 = wm*32 + mf*16 + r;
                split_tf32(Ab[m0*MSTR + kc],         ah[mf][0], al[mf][0]);
                split_tf32(Ab[(m0+8)*MSTR + kc],     ah[mf][1], al[mf][1]);
                split_tf32(Ab[m0*MSTR + kc + 4],     ah[mf][2], al[mf][2]);
                split_tf32(Ab[(m0+8)*MSTR + kc + 4], ah[mf][3], al[mf][3]);
            }
            uint32_t bh[4][2], bl[4][2];
            #pragma unroll
            for (int nf = 0; nf < 4; nf++) {
                int ncol = wn*32 + nf*8 + r;
                bh[nf][0] = uBh[kc*BSTR + ncol];
                bh[nf][1] = uBh[(kc+4)*BSTR + ncol];
                bl[nf][0] = uBl[kc*BSTR + ncol];
                bl[nf][1] = uBl[(kc+4)*BSTR + ncol];
            }
            #pragma unroll
            for (int mf = 0; mf < 2; mf++)
                #pragma unroll
                for (int nf = 0; nf < 4; nf++) {
                    mma_tf32(C[mf][nf], ah[mf], bh[nf]);
                    mma_tf32(C[mf][nf], ah[mf], bl[nf]);
                    mma_tf32(C[mf][nf], al[mf], bh[nf]);
                }
        }
        __syncthreads();
    }

    // ---- epilogue: bounce through smem, write packed splits + norms ----
    float* Ts = psm;                 // 128 x 65 fp32
    #pragma unroll
    for (int mf = 0; mf < 2; mf++) {
        int s = wm*32 + mf*16 + r;
        #pragma unroll
        for (int nf = 0; nf < 4; nf++) {
            int n = wn*32 + nf*8 + 2*cc;
            Ts[s*65 + n]         = C[mf][nf][0];
            Ts[s*65 + n + 1]     = C[mf][nf][1];
            Ts[(s+8)*65 + n]     = C[mf][nf][2];
            Ts[(s+8)*65 + n + 1] = C[mf][nf][3];
        }
    }
    __syncthreads();

    if (which < 2) {
        uint32_t* dsth = (which == 0) ? g_Qph : g_Kph;
        uint32_t* dstl = (which == 0) ? g_Qpl : g_Kpl;
        float* nrm = (which == 0) ? g_q2 : g_k2;
        const int sc = tid & 127;
        const int kh = tid >> 7;          // k-half of the 64-col block
        float psum = 0.0f;
        #pragma unroll
        for (int i = 0; i < 16; i++) {
            int n0 = kh*32 + 2*i;
            float v0 = Ts[sc*65 + n0];
            float v1 = Ts[sc*65 + n0 + 1];
            psum += v0*v0 + v1*v1;
            uint32_t hi, lo;
            split2_bf16(v0, v1, hi, lo);
            size_t oi = ((size_t)(b*(Dd/2) + (col0 + n0) >> 1) + 0);
            oi = ((size_t)(b*(Dd/2) + ((col0 + n0) >> 1)))*Ss + s_in + sc;
            dsth[oi] = hi;
            dstl[oi] = lo;
        }
        atomicAdd(&nrm[row0 + sc], psum);
    } else {
        for (int l = tid; l < 64*64; l += 256) {
            int kc = l >> 6, pr = l & 63;
            float v0 = Ts[(2*pr)*65 + kc];
            float v1 = Ts[(2*pr + 1)*65 + kc];
            uint32_t hi, lo;
            split2_bf16(v0, v1, hi, lo);
            size_t oi = ((size_t)(b*Dd + col0 + kc))*(Ss/2) + (s_in >> 1) + pr;
            g_Vph[oi] = hi;
            g_Vpl[oi] = lo;
        }
    }
}

// ---------------------------------------------------------------------------
// Kernel 2 (fused attn): Phase A: S = QK^T via split-bf16 m16n8k16 with
// PRE-SPLIT packed operands — cp.async double-buffered, fragments are plain
// LDS.32, zero conversion ALU. Epilogue A -> P split-bf16 in smem.
// Phase B: per 64-wide d-chunk, stage both V tiles, 96 MMAs, atomicAdd.
// grid: (16, 16, Bb*Hh)  block: 256
// ---------------------------------------------------------------------------
#define QPSTR 136   // Q pairs [kp][s] stride (u32): bank = 8cc+r, 16B-aligned
#define KPSTR 72    // K pairs [kp][t] stride
#define PSTR 36
#define VSTR 36
#define U_OFF 18432
// Phase A U per buffer (4480 u32): Qh@0(1088) Ql@1088 K0h@2176(576) K0l@2752
//   K1h@3328 K1l@3904.  Two buffers {0,4480} -> 8960 <= 9216.
// Phase B U: Vh {0,4608}, Vl {2304,6912}
#define FUSED_SMEM ((18432 + 9216)*4)   // 110592 B

__global__ __launch_bounds__(256, 2) void fused_attn_kernel(
    const float* __restrict__ gamma, float* __restrict__ out)
{
    const int si = blockIdx.x;
    const int chunk = blockIdx.y;
    if (chunk > si) return;
    const int z = blockIdx.z;
    const int b = z >> 3, h = z & 7;
    const float gh = gamma[h];
    for (int h2 = 0; h2 < h; h2++)
        if (gamma[h2] == gh) return;           // leader only
    const float coef = -1.0f / (-2.0f * gh + 1e-6f);

    const int s0 = si * 128;
    const int t0a = chunk * 128;
    const int t0b = t0a + 64;

    extern __shared__ uint32_t smu[];
    uint32_t* Ph[2] = { smu,        smu + 9216 };
    uint32_t* Pl[2] = { smu + 4608, smu + 13824 };
    uint32_t* U = smu + U_OFF;
    const uint32_t ub = smem_to_u32((const void*)U);

    const int tid = threadIdx.x, lane = tid & 31, wid = tid >> 5;
    const int wm = wid & 3, wn = wid >> 2;
    const int r = lane >> 2, cc = lane & 3;

    const uint32_t* Qh_g = g_Qph + (size_t)b*(Dd/2)*Ss;
    const uint32_t* Ql_g = g_Qpl + (size_t)b*(Dd/2)*Ss;
    const uint32_t* Kh_g = g_Kph + (size_t)b*(Dd/2)*Ss;
    const uint32_t* Kl_g = g_Kpl + (size_t)b*(Dd/2)*Ss;

    // ---------------- Phase A: 16 slabs of 8 k-pairs (k16) ---------------
    float C0[2][4][4] = {}, C1[2][4][4] = {};

    #define QK_ISSUE(sl, buf) do { \
        const int kp0 = (sl)*8; \
        { int row = tid >> 5, ch = tid & 31; \
          size_t go = (size_t)(kp0 + row)*Ss + s0 + ch*4; \
          uint32_t d0 = ub + (uint32_t)((buf)*4480 + row*QPSTR + ch*4)*4u; \
          CP_ASYNC16(d0,          (const void*)(Qh_g + go)); \
          CP_ASYNC16(d0 + 1088*4, (const void*)(Ql_g + go)); } \
        for (int i = tid; i < 512; i += 256) { \
            int sub = i >> 7, rem = i & 127, row = rem >> 4, ch = rem & 15; \
            const uint32_t* sg = (sub & 1) ? Kl_g : Kh_g; \
            int t0_i = (sub >> 1) ? t0b : t0a; \
            size_t go = (size_t)(kp0 + row)*Ss + t0_i + ch*4; \
            CP_ASYNC16(ub + (uint32_t)((buf)*4480 + 2176 + sub*576 + row*KPSTR + ch*4)*4u, \
                       (const void*)(sg + go)); \
        } \
    } while (0)

    QK_ISSUE(0, 0); CP_COMMIT();

    for (int sl = 0; sl < 16; sl++) {
        if (sl + 1 < 16) { QK_ISSUE(sl + 1, (sl + 1) & 1); CP_COMMIT(); CP_WAIT(1); }
        else             { CP_WAIT(0); }
        __syncthreads();

        const uint32_t* Qbh = U + (sl & 1)*4480;
        const uint32_t* Qbl = Qbh + 1088;
        const uint32_t* K0h = Qbh + 2176;
        const uint32_t* K0l = Qbh + 2752;
        const uint32_t* K1h = Qbh + 3328;
        const uint32_t* K1l = Qbh + 3904;

        uint32_t ah[2][4], al[2][4];
        #pragma unroll
        for (int mf = 0; mf < 2; mf++) {
            int m0 = wm*32 + mf*16 + r;
            ah[mf][0] = Qbh[cc*QPSTR + m0];
            ah[mf][1] = Qbh[cc*QPSTR + m0 + 8];
            ah[mf][2] = Qbh[(cc+4)*QPSTR + m0];
            ah[mf][3] = Qbh[(cc+4)*QPSTR + m0 + 8];
            al[mf][0] = Qbl[cc*QPSTR + m0];
            al[mf][1] = Qbl[cc*QPSTR + m0 + 8];
            al[mf][2] = Qbl[(cc+4)*QPSTR + m0];
            al[mf][3] = Qbl[(cc+4)*QPSTR + m0 + 8];
        }
        {   // tile 0
            uint32_t bh[4][2], bl[4][2];
            #pragma unroll
            for (int nf = 0; nf < 4; nf++) {
                int ncol = wn*32 + nf*8 + r;
                bh[nf][0] = K0h[cc*KPSTR + ncol];
                bh[nf][1] = K0h[(cc+4)*KPSTR + ncol];
                bl[nf][0] = K0l[cc*KPSTR + ncol];
                bl[nf][1] = K0l[(cc+4)*KPSTR + ncol];
            }
            #pragma unroll
            for (int mf = 0; mf < 2; mf++)
                #pragma unroll
                for (int nf = 0; nf < 4; nf++) {
                    mma_bf16(C0[mf][nf], ah[mf], bh[nf]);
                    mma_bf16(C0[mf][nf], ah[mf], bl[nf]);
                    mma_bf16(C0[mf][nf], al[mf], bh[nf]);
                }
        }
        {   // tile 1
            uint32_t bh[4][2], bl[4][2];
            #pragma unroll
            for (int nf = 0; nf < 4; nf++) {
                int ncol = wn*32 + nf*8 + r;
                bh[nf][0] = K1h[cc*KPSTR + ncol];
                bh[nf][1] = K1h[(cc+4)*KPSTR + ncol];
                bl[nf][0] = K1l[cc*KPSTR + ncol];
                bl[nf][1] = K1l[(cc+4)*KPSTR + ncol];
            }
            #pragma unroll
            for (int mf = 0; mf < 2; mf++)
                #pragma unroll
                for (int nf = 0; nf < 4; nf++) {
                    mma_bf16(C1[mf][nf], ah[mf], bh[nf]);
                    mma_bf16(C1[mf][nf], ah[mf], bl[nf]);
                    mma_bf16(C1[mf][nf], al[mf], bh[nf]);
                }
        }
        __syncthreads();
    }

    // ---------------- Epilogue A: P = exp(coef * d2), split bf16 --------
    #pragma unroll
    for (int tl = 0; tl < 2; tl++) {
        const int t0 = tl ? t0b : t0a;
        float (*C)[4][4] = tl ? C1 : C0;
        #pragma unroll
        for (int mf = 0; mf < 2; mf++) {
            int sl2 = wm*32 + mf*16 + r;
            int sg = s0 + sl2;
            float q2a = g_q2[b*Ss + sg];
            float q2c = g_q2[b*Ss + sg + 8];
            #pragma unroll
            for (int nf = 0; nf < 4; nf++) {
                int tg = t0 + wn*32 + nf*8 + 2*cc;
                float k2a = g_k2[b*Ss + tg];
                float k2b = g_k2[b*Ss + tg + 1];
                float p00 = (tg     > sg) ? 0.0f : __expf(coef * fmaxf(q2a + k2a - 2.0f*C[mf][nf][0], 0.0f));
                float p01 = (tg + 1 > sg) ? 0.0f : __expf(coef * fmaxf(q2a + k2b - 2.0f*C[mf][nf][1], 0.0f));
                float p10 = (tg     > sg + 8) ? 0.0f : __expf(coef * fmaxf(q2c + k2a - 2.0f*C[mf][nf][2], 0.0f));
                float p11 = (tg + 1 > sg + 8) ? 0.0f : __expf(coef * fmaxf(q2c + k2b - 2.0f*C[mf][nf][3], 0.0f));
                int pidx = wn*16 + nf*4 + cc;
                uint32_t hi0, lo0, hi1, lo1;
                split2_bf16(p00, p01, hi0, lo0);
                split2_bf16(p10, p11, hi1, lo1);
                Ph[tl][sl2*PSTR + pidx]     = hi0;
                Ph[tl][(sl2+8)*PSTR + pidx] = hi1;
                Pl[tl][sl2*PSTR + pidx]     = lo0;
                Pl[tl][(sl2+8)*PSTR + pidx] = lo1;
            }
        }
    }
    __syncthreads();

    // ---------------- Phase B: OUT += P @ V^T per d-chunk ----------------
    uint32_t* Vh[2] = { U,        U + 4608 };
    uint32_t* Vl[2] = { U + 2304, U + 6912 };
    float* o = out + ((size_t)(b*Hh + h)*Ss)*Dd;

    for (int dch = 0; dch < 4; dch++) {
        for (int l = tid; l < 512; l += 256) {
            int d = l >> 3, c = l & 7;
            size_t gia = ((size_t)(b*Dd + dch*64 + d))*(Ss/2) + t0a/2 + c*4;
            size_t gib = ((size_t)(b*Dd + dch*64 + d))*(Ss/2) + t0b/2 + c*4;
            *(uint4*)&Vh[0][d*VSTR + c*4] = *(const uint4*)(g_Vph + gia);
            *(uint4*)&Vl[0][d*VSTR + c*4] = *(const uint4*)(g_Vpl + gia);
            *(uint4*)&Vh[1][d*VSTR + c*4] = *(const uint4*)(g_Vph + gib);
            *(uint4*)&Vl[1][d*VSTR + c*4] = *(const uint4*)(g_Vpl + gib);
        }
        __syncthreads();

        float C[2][4][4] = {};
        #pragma unroll
        for (int tl = 0; tl < 2; tl++) {
            #pragma unroll
            for (int ks = 0; ks < 4; ks++) {
                const int pc = ks*8 + cc;
                uint32_t ah[2][4], al[2][4];
                #pragma unroll
                for (int mf = 0; mf < 2; mf++) {
                    int srow = wm*32 + mf*16 + r;
                    ah[mf][0] = Ph[tl][srow*PSTR + pc];
                    ah[mf][1] = Ph[tl][(srow+8)*PSTR + pc];
                    ah[mf][2] = Ph[tl][srow*PSTR + pc + 4];
                    ah[mf][3] = Ph[tl][(srow+8)*PSTR + pc + 4];
                    al[mf][0] = Pl[tl][srow*PSTR + pc];
                    al[mf][1] = Pl[tl][(srow+8)*PSTR + pc];
                    al[mf][2] = Pl[tl][srow*PSTR + pc + 4];
                    al[mf][3] = Pl[tl][(srow+8)*PSTR + pc + 4];
                }
                uint32_t bh[4][2], bl[4][2];
                #pragma unroll
                for (int nf = 0; nf < 4; nf++) {
                    int dcol = wn*32 + nf*8 + r;
                    bh[nf][0] = Vh[tl][dcol*VSTR + pc];
                    bh[nf][1] = Vh[tl][dcol*VSTR + pc + 4];
                    bl[nf][0] = Vl[tl][dcol*VSTR + pc];
                    bl[nf][1] = Vl[tl][dcol*VSTR + pc + 4];
                }
                #pragma unroll
                for (int mf = 0; mf < 2; mf++)
                    #pragma unroll
                    for (int nf = 0; nf < 4; nf++) {
                        mma_bf16(C[mf][nf], ah[mf], bh[nf]);
                        mma_bf16(C[mf][nf], ah[mf], bl[nf]);
                        mma_bf16(C[mf][nf], al[mf], bh[nf]);
                    }
            }
        }
        #pragma unroll
        for (int mf = 0; mf < 2; mf++) {
            int s = s0 + wm*32 + mf*16 + r;
            #pragma unroll
            for (int nf = 0; nf < 4; nf++) {
                int d = dch*64 + wn*32 + nf*8 + 2*cc;
                atomicAdd(&o[(size_t)s*Dd + d],         C[mf][nf][0]);
                atomicAdd(&o[(size_t)s*Dd + d + 1],     C[mf][nf][1]);
                atomicAdd(&o[(size_t)(s+8)*Dd + d],     C[mf][nf][2]);
                atomicAdd(&o[(size_t)(s+8)*Dd + d + 1], C[mf][nf][3]);
            }
        }
        if (dch < 3) __syncthreads();   // last iter: nothing reads smem after
    }
}

// ---------------------------------------------------------------------------
// Kernel 3: broadcast — leader reads once, stores to every duplicate head.
// grid: ((Ss*Dd)/1024, Hh, Bb)  block: 256
// ---------------------------------------------------------------------------
__global__ __launch_bounds__(256) void bcast_kernel(
    const float* __restrict__ gamma, float* __restrict__ out)
{
    const int h = blockIdx.y, b = blockIdx.z;
    const float gh = gamma[h];
    for (int h2 = 0; h2 < h; h2++)
        if (gamma[h2] == gh) return;           // only leaders broadcast

    size_t idx = ((size_t)blockIdx.x * 256 + threadIdx.x) * 4;
    const float4 v = *(const float4*)&out[((size_t)(b*Hh + h)*Ss)*Dd + idx];
    for (int h2 = h + 1; h2 < Hh; h2++) {
        if (gamma[h2] != gh) continue;
        *(float4*)&out[((size_t)(b*Hh + h2)*Ss)*Dd + idx] = v;
    }
}

// ---------------------------------------------------------------------------
extern "C" void kernel_launch(void* const* d_in, const int* in_sizes, int n_in,
                              void* d_out, int out_size)
{
    // metadata order: x, e, p, W_q, W_k, W_v, gamma
    const float* e     = (const float*)d_in[1];
    const float* p     = (const float*)d_in[2];
    const float* Wq    = (const float*)d_in[3];
    const float* Wk    = (const float*)d_in[4];
    const float* Wv    = (const float*)d_in[5];
    const float* gamma = (const float*)d_in[6];
    float* out = (float*)d_out;

    static bool init_done = false;
    static void *q2p = nullptr, *k2p = nullptr;
    if (!init_done) {
        cudaFuncSetAttribute(proj_mma_kernel,
                             cudaFuncAttributeMaxDynamicSharedMemorySize, PROJ_SMEM);
        cudaFuncSetAttribute(fused_attn_kernel,
                             cudaFuncAttributeMaxDynamicSharedMemorySize, FUSED_SMEM);
        cudaGetSymbolAddress(&q2p, g_q2);
        cudaGetSymbolAddress(&k2p, g_k2);
        init_done = true;
    }

    cudaMemsetAsync(q2p, 0, NR * sizeof(float));
    cudaMemsetAsync(k2p, 0, NR * sizeof(float));

    dim3 gz((Ss*Dd)/1024, Hh, Bb);
    zero_kernel<<<gz, 256>>>(gamma, out);

    dim3 gw(Dd*Dd/256, 3);
    wsplit_kernel<<<gw, 256>>>(Wq, Wk, Wv);

    dim3 gproj(NR/128, Dd/64, 3);
    proj_mma_kernel<<<gproj, 256, PROJ_SMEM>>>(p, e);

    dim3 gf(16, 16, Bb*Hh);
    fused_attn_kernel<<<gf, 256, FUSED_SMEM>>>(gamma, out);

    dim3 gb((Ss*Dd)/1024, Hh, Bb);
    bcast_kernel<<<gb, 256>>>(gamma, out);
}

// round 17
// speedup vs baseline: 1.2838x; 1.0901x over previous
#include <cuda_runtime.h>
#include <cuda_bf16.h>
#include <cstdint>

// Problem constants
#define Bb 2
#define Ss 2048
#define Dd 256
#define Hh 8
#define NR (Bb*Ss)

// Scratch: pre-split packed operands + norms
// Q/K: bf16x2 pairs over adjacent k, layout [b][k/2][s]
__device__ __align__(16) uint32_t g_Qph[Bb*(Dd/2)*Ss], g_Qpl[Bb*(Dd/2)*Ss];
__device__ __align__(16) uint32_t g_Kph[Bb*(Dd/2)*Ss], g_Kpl[Bb*(Dd/2)*Ss];
// V: bf16x2 pairs over adjacent t, layout [b][d][t/2]
__device__ __align__(16) uint32_t g_Vph[Bb*Dd*(Ss/2)], g_Vpl[Bb*Dd*(Ss/2)];
__device__ float g_q2[NR];
__device__ float g_k2[NR];
// pre-split inputs p/e: bf16x2 pairs over adjacent k, [which][row][k/2]
__device__ __align__(16) uint32_t g_Aph[2*NR*(Dd/2)], g_Apl[2*NR*(Dd/2)];
// pre-split weights: bf16x2 pairs over adjacent k, [which][k/2][n]
__device__ __align__(16) uint32_t g_Wph[3*(Dd/2)*Dd], g_Wpl[3*(Dd/2)*Dd];

// ===================== helpers =====================
__device__ __forceinline__ void mma_bf16(float* c, const uint32_t* a, const uint32_t* b) {
    asm volatile(
        "mma.sync.aligned.m16n8k16.row.col.f32.bf16.bf16.f32 "
        "{%0,%1,%2,%3}, {%4,%5,%6,%7}, {%8,%9}, {%0,%1,%2,%3};"
        : "+f"(c[0]), "+f"(c[1]), "+f"(c[2]), "+f"(c[3])
        : "r"(a[0]), "r"(a[1]), "r"(a[2]), "r"(a[3]), "r"(b[0]), "r"(b[1]));
}
__device__ __forceinline__ uint32_t pack_bf16x2(float lo_val, float hi_val) {
    __nv_bfloat16 l = __float2bfloat16(lo_val);
    __nv_bfloat16 h = __float2bfloat16(hi_val);
    return (uint32_t)__bfloat16_as_ushort(l) | ((uint32_t)__bfloat16_as_ushort(h) << 16);
}
// split pair (e0 -> low half, e1 -> high half) into bf16 hi + residual lo words
__device__ __forceinline__ void split2_bf16(float e0, float e1, uint32_t& hi, uint32_t& lo) {
    __nv_bfloat16 h0 = __float2bfloat16(e0);
    __nv_bfloat16 h1 = __float2bfloat16(e1);
    hi = (uint32_t)__bfloat16_as_ushort(h0) | ((uint32_t)__bfloat16_as_ushort(h1) << 16);
    lo = pack_bf16x2(e0 - __bfloat162float(h0), e1 - __bfloat162float(h1));
}
__device__ __forceinline__ uint32_t smem_to_u32(const void* smem_ptr) {
    uint32_t addr;
    asm("{ .reg .u64 tmp; cvta.to.shared.u64 tmp, %1; cvt.u32.u64 %0, tmp; }"
        : "=r"(addr) : "l"(smem_ptr));
    return addr;
}
#define CP_ASYNC16(dst, src) \
    asm volatile("cp.async.cg.shared.global [%0], [%1], 16;" :: "r"(dst), "l"(src))
#define CP_COMMIT() asm volatile("cp.async.commit_group;" ::: "memory")
#define CP_WAIT(n)  asm volatile("cp.async.wait_group %0;" :: "n"(n) : "memory")

// ---------------------------------------------------------------------------
// Kernel 0a: pre-split inputs p/e into packed bf16x2 pairs [which][row][kp].
// Each thread handles 2 adjacent pairs (one float4). grid: (NR*Dd/1024, 2)
// ---------------------------------------------------------------------------
__global__ __launch_bounds__(256) void insplit_kernel(
    const float* __restrict__ p, const float* __restrict__ e)
{
    const int which = blockIdx.y;
    const float* src = which ? e : p;
    size_t i = (size_t)blockIdx.x * 256 + threadIdx.x;   // float4 index
    float4 v = ((const float4*)src)[i];
    uint32_t hi0, lo0, hi1, lo1;
    split2_bf16(v.x, v.y, hi0, lo0);
    split2_bf16(v.z, v.w, hi1, lo1);
    size_t o = (size_t)which * NR*(Dd/2) + i*2;
    g_Aph[o] = hi0;  g_Aph[o+1] = hi1;
    g_Apl[o] = lo0;  g_Apl[o+1] = lo1;
}

// ---------------------------------------------------------------------------
// Kernel 0b: pre-split weights into packed bf16x2 pairs [which][kp][n].
// grid: (Dd*Dd/512, 3)  block: 256  (each thread = one (kp, n) output word)
// ---------------------------------------------------------------------------
__global__ __launch_bounds__(256) void wsplit_kernel(
    const float* __restrict__ Wq, const float* __restrict__ Wk,
    const float* __restrict__ Wv)
{
    const int which = blockIdx.y;
    const float* W = (which == 0) ? Wq : (which == 1) ? Wk : Wv;
    int i = blockIdx.x * 256 + threadIdx.x;    // pair index: kp*Dd + n
    int kp = i >> 8, n = i & 255;
    float v0 = W[(2*kp)*Dd + n];
    float v1 = W[(2*kp + 1)*Dd + n];
    uint32_t hi, lo;
    split2_bf16(v0, v1, hi, lo);
    g_Wph[(size_t)which*(Dd/2)*Dd + i] = hi;
    g_Wpl[(size_t)which*(Dd/2)*Dd + i] = lo;
}

// ---------------------------------------------------------------------------
// Kernel 0c: zero only LEADER-head output slices (atomicAdd targets).
// grid: ((Ss*Dd)/1024, Hh, Bb)  block: 256
// ---------------------------------------------------------------------------
__global__ __launch_bounds__(256) void zero_kernel(
    const float* __restrict__ gamma, float* __restrict__ out)
{
    const int h = blockIdx.y, b = blockIdx.z;
    const float gh = gamma[h];
    for (int h2 = 0; h2 < h; h2++)
        if (gamma[h2] == gh) return;           // not a leader
    size_t idx = ((size_t)blockIdx.x * 256 + threadIdx.x) * 4;
    *(float4*)&out[((size_t)(b*Hh + h)*Ss)*Dd + idx] = make_float4(0.f, 0.f, 0.f, 0.f);
}

// ---------------------------------------------------------------------------
// Kernel 1: ALL-bf16 split MMA projections (m16n8k16, 3-product), operands
// pre-split/packed; staging is pure cp.async, zero conversion ALU in loop.
// Block tile 128m x 64n, warp tile 32x32 (4x2 warps), 8 slabs of 32 k (16 kp).
// Epilogue writes packed bf16x2 operands for the fused kernel + norms.
// grid: (NR/128, Dd/64, 3)  block: 256
// ---------------------------------------------------------------------------
#define ASTRP 20    // A pairs [m][kp] stride (u32): bank = 20r+cc, 16B-aligned
#define BSTRP 72    // B pairs [kp][n] stride (u32): bank = 8cc+r
// smem u32: Ah0@0(2560) Al0@2560 Ah1@5120 Al1@7680
//           Bh0@10240(1152) Bl0@11392 Bh1@12544 Bl1@13696 -> 14848
#define PROJ_SMEM (14848*4)   // 59392 B  (epilogue Ts needs 8320 floats, fits)

__global__ __launch_bounds__(256, 2) void proj_mma_kernel()
{
    const int which = blockIdx.z;
    const uint32_t* Ah_g = g_Aph + (size_t)((which == 2) ? 1 : 0) * NR*(Dd/2);
    const uint32_t* Al_g = g_Apl + (size_t)((which == 2) ? 1 : 0) * NR*(Dd/2);
    const uint32_t* Wh_g = g_Wph + (size_t)which*(Dd/2)*Dd;
    const uint32_t* Wl_g = g_Wpl + (size_t)which*(Dd/2)*Dd;

    const int row0 = blockIdx.x * 128;
    const int col0 = blockIdx.y * 64;
    const int b    = row0 >> 11;
    const int s_in = row0 & (Ss - 1);

    extern __shared__ uint32_t psu[];
    const uint32_t smb = smem_to_u32(psu);

    const int tid = threadIdx.x, lane = tid & 31, wid = tid >> 5;
    const int wm = wid & 3, wn = wid >> 2;
    const int r = lane >> 2, cc = lane & 3;

    float C[2][4][4] = {};

    #define P_ISSUE(sl, buf) do { \
        const int kp0 = (sl)*16; \
        for (int i = tid; i < 512; i += 256) { \
            int row = i >> 2, ch = i & 3; \
            size_t go = (size_t)(row0 + row)*(Dd/2) + kp0 + ch*4; \
            uint32_t d0 = smb + (uint32_t)((buf)*5120 + row*ASTRP + ch*4)*4u; \
            CP_ASYNC16(d0,          (const void*)(Ah_g + go)); \
            CP_ASYNC16(d0 + 2560*4, (const void*)(Al_g + go)); \
        } \
        for (int i = tid; i < 256; i += 256) { \
            int row = i >> 4, ch = i & 15; \
            size_t go = (size_t)(kp0 + row)*Dd + col0 + ch*4; \
            uint32_t d0 = smb + (uint32_t)(10240 + (buf)*2304 + row*BSTRP + ch*4)*4u; \
            CP_ASYNC16(d0,          (const void*)(Wh_g + go)); \
            CP_ASYNC16(d0 + 1152*4, (const void*)(Wl_g + go)); \
        } \
    } while (0)

    P_ISSUE(0, 0); CP_COMMIT();

    for (int sl = 0; sl < 8; sl++) {
        if (sl + 1 < 8) { P_ISSUE(sl + 1, (sl + 1) & 1); CP_COMMIT(); CP_WAIT(1); }
        else            { CP_WAIT(0); }
        __syncthreads();

        const uint32_t* Ah = psu + (sl & 1)*5120;
        const uint32_t* Al = Ah + 2560;
        const uint32_t* Bh = psu + 10240 + (sl & 1)*2304;
        const uint32_t* Bl = Bh + 1152;

        #pragma unroll
        for (int ks = 0; ks < 2; ks++) {
            const int kpc = ks*8 + cc;
            uint32_t ah[2][4], al[2][4];
            #pragma unroll
            for (int mf = 0; mf < 2; mf++) {
                int m0 = wm*32 + mf*16 + r;
                ah[mf][0] = Ah[m0*ASTRP + kpc];
                ah[mf][1] = Ah[(m0+8)*ASTRP + kpc];
                ah[mf][2] = Ah[m0*ASTRP + kpc + 4];
                ah[mf][3] = Ah[(m0+8)*ASTRP + kpc + 4];
                al[mf][0] = Al[m0*ASTRP + kpc];
                al[mf][1] = Al[(m0+8)*ASTRP + kpc];
                al[mf][2] = Al[m0*ASTRP + kpc + 4];
                al[mf][3] = Al[(m0+8)*ASTRP + kpc + 4];
            }
            uint32_t bh[4][2], bl[4][2];
            #pragma unroll
            for (int nf = 0; nf < 4; nf++) {
                int ncol = wn*32 + nf*8 + r;
                bh[nf][0] = Bh[kpc*BSTRP + ncol];
                bh[nf][1] = Bh[(kpc+4)*BSTRP + ncol];
                bl[nf][0] = Bl[kpc*BSTRP + ncol];
                bl[nf][1] = Bl[(kpc+4)*BSTRP + ncol];
            }
            #pragma unroll
            for (int mf = 0; mf < 2; mf++)
                #pragma unroll
                for (int nf = 0; nf < 4; nf++) {
                    mma_bf16(C[mf][nf], ah[mf], bh[nf]);
                    mma_bf16(C[mf][nf], ah[mf], bl[nf]);
                    mma_bf16(C[mf][nf], al[mf], bh[nf]);
                }
        }
        __syncthreads();
    }

    // ---- epilogue: bounce through smem, write packed splits + norms ----
    float* Ts = (float*)psu;         // 128 x 65 fp32 (8320 <= 14848)
    #pragma unroll
    for (int mf = 0; mf < 2; mf++) {
        int s = wm*32 + mf*16 + r;
        #pragma unroll
        for (int nf = 0; nf < 4; nf++) {
            int n = wn*32 + nf*8 + 2*cc;
            Ts[s*65 + n]         = C[mf][nf][0];
            Ts[s*65 + n + 1]     = C[mf][nf][1];
            Ts[(s+8)*65 + n]     = C[mf][nf][2];
            Ts[(s+8)*65 + n + 1] = C[mf][nf][3];
        }
    }
    __syncthreads();

    if (which < 2) {
        uint32_t* dsth = (which == 0) ? g_Qph : g_Kph;
        uint32_t* dstl = (which == 0) ? g_Qpl : g_Kpl;
        float* nrm = (which == 0) ? g_q2 : g_k2;
        const int sc = tid & 127;
        const int kh = tid >> 7;          // k-half of the 64-col block
        float psum = 0.0f;
        #pragma unroll
        for (int i = 0; i < 16; i++) {
            int n0 = kh*32 + 2*i;
            float v0 = Ts[sc*65 + n0];
            float v1 = Ts[sc*65 + n0 + 1];
            psum += v0*v0 + v1*v1;
            uint32_t hi, lo;
            split2_bf16(v0, v1, hi, lo);
            size_t oi = ((size_t)(b*(Dd/2) + ((col0 + n0) >> 1)))*Ss + s_in + sc;
            dsth[oi] = hi;
            dstl[oi] = lo;
        }
        atomicAdd(&nrm[row0 + sc], psum);
    } else {
        for (int l = tid; l < 64*64; l += 256) {
            int kc = l >> 6, pr = l & 63;
            float v0 = Ts[(2*pr)*65 + kc];
            float v1 = Ts[(2*pr + 1)*65 + kc];
            uint32_t hi, lo;
            split2_bf16(v0, v1, hi, lo);
            size_t oi = ((size_t)(b*Dd + col0 + kc))*(Ss/2) + (s_in >> 1) + pr;
            g_Vph[oi] = hi;
            g_Vpl[oi] = lo;
        }
    }
}

// ---------------------------------------------------------------------------
// Kernel 2 (fused attn) [R16-proven, unchanged]: Phase A: S = QK^T via
// split-bf16 m16n8k16 with pre-split packed operands — cp.async double-
// buffered, fragments are plain LDS.32, zero conversion ALU.
// Epilogue A -> P split-bf16 in smem. Phase B: per 64-wide d-chunk, stage
// both V tiles, 96 MMAs, atomicAdd. grid: (16, 16, Bb*Hh)  block: 256
// ---------------------------------------------------------------------------
#define QPSTR 136   // Q pairs [kp][s] stride (u32)
#define KPSTR 72    // K pairs [kp][t] stride
#define PSTR 36
#define VSTR 36
#define U_OFF 18432
#define FUSED_SMEM ((18432 + 9216)*4)   // 110592 B

__global__ __launch_bounds__(256, 2) void fused_attn_kernel(
    const float* __restrict__ gamma, float* __restrict__ out)
{
    const int si = blockIdx.x;
    const int chunk = blockIdx.y;
    if (chunk > si) return;
    const int z = blockIdx.z;
    const int b = z >> 3, h = z & 7;
    const float gh = gamma[h];
    for (int h2 = 0; h2 < h; h2++)
        if (gamma[h2] == gh) return;           // leader only
    const float coef = -1.0f / (-2.0f * gh + 1e-6f);

    const int s0 = si * 128;
    const int t0a = chunk * 128;
    const int t0b = t0a + 64;

    extern __shared__ uint32_t smu[];
    uint32_t* Ph[2] = { smu,        smu + 9216 };
    uint32_t* Pl[2] = { smu + 4608, smu + 13824 };
    uint32_t* U = smu + U_OFF;
    const uint32_t ub = smem_to_u32((const void*)U);

    const int tid = threadIdx.x, lane = tid & 31, wid = tid >> 5;
    const int wm = wid & 3, wn = wid >> 2;
    const int r = lane >> 2, cc = lane & 3;

    const uint32_t* Qh_g = g_Qph + (size_t)b*(Dd/2)*Ss;
    const uint32_t* Ql_g = g_Qpl + (size_t)b*(Dd/2)*Ss;
    const uint32_t* Kh_g = g_Kph + (size_t)b*(Dd/2)*Ss;
    const uint32_t* Kl_g = g_Kpl + (size_t)b*(Dd/2)*Ss;

    // ---------------- Phase A: 16 slabs of 8 k-pairs (k16) ---------------
    float C0[2][4][4] = {}, C1[2][4][4] = {};

    #define QK_ISSUE(sl, buf) do { \
        const int kp0 = (sl)*8; \
        { int row = tid >> 5, ch = tid & 31; \
          size_t go = (size_t)(kp0 + row)*Ss + s0 + ch*4; \
          uint32_t d0 = ub + (uint32_t)((buf)*4480 + row*QPSTR + ch*4)*4u; \
          CP_ASYNC16(d0,          (const void*)(Qh_g + go)); \
          CP_ASYNC16(d0 + 1088*4, (const void*)(Ql_g + go)); } \
        for (int i = tid; i < 512; i += 256) { \
            int sub = i >> 7, rem = i & 127, row = rem >> 4, ch = rem & 15; \
            const uint32_t* sg = (sub & 1) ? Kl_g : Kh_g; \
            int t0_i = (sub >> 1) ? t0b : t0a; \
            size_t go = (size_t)(kp0 + row)*Ss + t0_i + ch*4; \
            CP_ASYNC16(ub + (uint32_t)((buf)*4480 + 2176 + sub*576 + row*KPSTR + ch*4)*4u, \
                       (const void*)(sg + go)); \
        } \
    } while (0)

    QK_ISSUE(0, 0); CP_COMMIT();

    for (int sl = 0; sl < 16; sl++) {
        if (sl + 1 < 16) { QK_ISSUE(sl + 1, (sl + 1) & 1); CP_COMMIT(); CP_WAIT(1); }
        else             { CP_WAIT(0); }
        __syncthreads();

        const uint32_t* Qbh = U + (sl & 1)*4480;
        const uint32_t* Qbl = Qbh + 1088;
        const uint32_t* K0h = Qbh + 2176;
        const uint32_t* K0l = Qbh + 2752;
        const uint32_t* K1h = Qbh + 3328;
        const uint32_t* K1l = Qbh + 3904;

        uint32_t ah[2][4], al[2][4];
        #pragma unroll
        for (int mf = 0; mf < 2; mf++) {
            int m0 = wm*32 + mf*16 + r;
            ah[mf][0] = Qbh[cc*QPSTR + m0];
            ah[mf][1] = Qbh[cc*QPSTR + m0 + 8];
            ah[mf][2] = Qbh[(cc+4)*QPSTR + m0];
            ah[mf][3] = Qbh[(cc+4)*QPSTR + m0 + 8];
            al[mf][0] = Qbl[cc*QPSTR + m0];
            al[mf][1] = Qbl[cc*QPSTR + m0 + 8];
            al[mf][2] = Qbl[(cc+4)*QPSTR + m0];
            al[mf][3] = Qbl[(cc+4)*QPSTR + m0 + 8];
        }
        {   // tile 0
            uint32_t bh[4][2], bl[4][2];
            #pragma unroll
            for (int nf = 0; nf < 4; nf++) {
                int ncol = wn*32 + nf*8 + r;
                bh[nf][0] = K0h[cc*KPSTR + ncol];
                bh[nf][1] = K0h[(cc+4)*KPSTR + ncol];
                bl[nf][0] = K0l[cc*KPSTR + ncol];
                bl[nf][1] = K0l[(cc+4)*KPSTR + ncol];
            }
            #pragma unroll
            for (int mf = 0; mf < 2; mf++)
                #pragma unroll
                for (int nf = 0; nf < 4; nf++) {
                    mma_bf16(C0[mf][nf], ah[mf], bh[nf]);
                    mma_bf16(C0[mf][nf], ah[mf], bl[nf]);
                    mma_bf16(C0[mf][nf], al[mf], bh[nf]);
                }
        }
        {   // tile 1
            uint32_t bh[4][2], bl[4][2];
            #pragma unroll
            for (int nf = 0; nf < 4; nf++) {
                int ncol = wn*32 + nf*8 + r;
                bh[nf][0] = K1h[cc*KPSTR + ncol];
                bh[nf][1] = K1h[(cc+4)*KPSTR + ncol];
                bl[nf][0] = K1l[cc*KPSTR + ncol];
                bl[nf][1] = K1l[(cc+4)*KPSTR + ncol];
            }
            #pragma unroll
            for (int mf = 0; mf < 2; mf++)
                #pragma unroll
                for (int nf = 0; nf < 4; nf++) {
                    mma_bf16(C1[mf][nf], ah[mf], bh[nf]);
                    mma_bf16(C1[mf][nf], ah[mf], bl[nf]);
                    mma_bf16(C1[mf][nf], al[mf], bh[nf]);
                }
        }
        __syncthreads();
    }

    // ---------------- Epilogue A: P = exp(coef * d2), split bf16 --------
    #pragma unroll
    for (int tl = 0; tl < 2; tl++) {
        const int t0 = tl ? t0b : t0a;
        float (*C)[4][4] = tl ? C1 : C0;
        #pragma unroll
        for (int mf = 0; mf < 2; mf++) {
            int sl2 = wm*32 + mf*16 + r;
            int sg = s0 + sl2;
            float q2a = g_q2[b*Ss + sg];
            float q2c = g_q2[b*Ss + sg + 8];
            #pragma unroll
            for (int nf = 0; nf < 4; nf++) {
                int tg = t0 + wn*32 + nf*8 + 2*cc;
                float k2a = g_k2[b*Ss + tg];
                float k2b = g_k2[b*Ss + tg + 1];
                float p00 = (tg     > sg) ? 0.0f : __expf(coef * fmaxf(q2a + k2a - 2.0f*C[mf][nf][0], 0.0f));
                float p01 = (tg + 1 > sg) ? 0.0f : __expf(coef * fmaxf(q2a + k2b - 2.0f*C[mf][nf][1], 0.0f));
                float p10 = (tg     > sg + 8) ? 0.0f : __expf(coef * fmaxf(q2c + k2a - 2.0f*C[mf][nf][2], 0.0f));
                float p11 = (tg + 1 > sg + 8) ? 0.0f : __expf(coef * fmaxf(q2c + k2b - 2.0f*C[mf][nf][3], 0.0f));
                int pidx = wn*16 + nf*4 + cc;
                uint32_t hi0, lo0, hi1, lo1;
                split2_bf16(p00, p01, hi0, lo0);
                split2_bf16(p10, p11, hi1, lo1);
                Ph[tl][sl2*PSTR + pidx]     = hi0;
                Ph[tl][(sl2+8)*PSTR + pidx] = hi1;
                Pl[tl][sl2*PSTR + pidx]     = lo0;
                Pl[tl][(sl2+8)*PSTR + pidx] = lo1;
            }
        }
    }
    __syncthreads();

    // ---------------- Phase B: OUT += P @ V^T per d-chunk ----------------
    uint32_t* Vh[2] = { U,        U + 4608 };
    uint32_t* Vl[2] = { U + 2304, U + 6912 };
    float* o = out + ((size_t)(b*Hh + h)*Ss)*Dd;

    for (int dch = 0; dch < 4; dch++) {
        for (int l = tid; l < 512; l += 256) {
            int d = l >> 3, c = l & 7;
            size_t gia = ((size_t)(b*Dd + dch*64 + d))*(Ss/2) + t0a/2 + c*4;
            size_t gib = ((size_t)(b*Dd + dch*64 + d))*(Ss/2) + t0b/2 + c*4;
            *(uint4*)&Vh[0][d*VSTR + c*4] = *(const uint4*)(g_Vph + gia);
            *(uint4*)&Vl[0][d*VSTR + c*4] = *(const uint4*)(g_Vpl + gia);
            *(uint4*)&Vh[1][d*VSTR + c*4] = *(const uint4*)(g_Vph + gib);
            *(uint4*)&Vl[1][d*VSTR + c*4] = *(const uint4*)(g_Vpl + gib);
        }
        __syncthreads();

        float C[2][4][4] = {};
        #pragma unroll
        for (int tl = 0; tl < 2; tl++) {
            #pragma unroll
            for (int ks = 0; ks < 4; ks++) {
                const int pc = ks*8 + cc;
                uint32_t ah[2][4], al[2][4];
                #pragma unroll
                for (int mf = 0; mf < 2; mf++) {
                    int srow = wm*32 + mf*16 + r;
                    ah[mf][0] = Ph[tl][srow*PSTR + pc];
                    ah[mf][1] = Ph[tl][(srow+8)*PSTR + pc];
                    ah[mf][2] = Ph[tl][srow*PSTR + pc + 4];
                    ah[mf][3] = Ph[tl][(srow+8)*PSTR + pc + 4];
                    al[mf][0] = Pl[tl][srow*PSTR + pc];
                    al[mf][1] = Pl[tl][(srow+8)*PSTR + pc];
                    al[mf][2] = Pl[tl][srow*PSTR + pc + 4];
                    al[mf][3] = Pl[tl][(srow+8)*PSTR + pc + 4];
                }
                uint32_t bh[4][2], bl[4][2];
                #pragma unroll
                for (int nf = 0; nf < 4; nf++) {
                    int dcol = wn*32 + nf*8 + r;
                    bh[nf][0] = Vh[tl][dcol*VSTR + pc];
                    bh[nf][1] = Vh[tl][dcol*VSTR + pc + 4];
                    bl[nf][0] = Vl[tl][dcol*VSTR + pc];
                    bl[nf][1] = Vl[tl][dcol*VSTR + pc + 4];
                }
                #pragma unroll
                for (int mf = 0; mf < 2; mf++)
                    #pragma unroll
                    for (int nf = 0; nf < 4; nf++) {
                        mma_bf16(C[mf][nf], ah[mf], bh[nf]);
                        mma_bf16(C[mf][nf], ah[mf], bl[nf]);
                        mma_bf16(C[mf][nf], al[mf], bh[nf]);
                    }
            }
        }
        #pragma unroll
        for (int mf = 0; mf < 2; mf++) {
            int s = s0 + wm*32 + mf*16 + r;
            #pragma unroll
            for (int nf = 0; nf < 4; nf++) {
                int d = dch*64 + wn*32 + nf*8 + 2*cc;
                atomicAdd(&o[(size_t)s*Dd + d],         C[mf][nf][0]);
                atomicAdd(&o[(size_t)s*Dd + d + 1],     C[mf][nf][1]);
                atomicAdd(&o[(size_t)(s+8)*Dd + d],     C[mf][nf][2]);
                atomicAdd(&o[(size_t)(s+8)*Dd + d + 1], C[mf][nf][3]);
            }
        }
        if (dch < 3) __syncthreads();   // last iter: nothing reads smem after
    }
}

// ---------------------------------------------------------------------------
// Kernel 3: broadcast — leader reads once, stores to every duplicate head.
// grid: ((Ss*Dd)/1024, Hh, Bb)  block: 256
// ---------------------------------------------------------------------------
__global__ __launch_bounds__(256) void bcast_kernel(
    const float* __restrict__ gamma, float* __restrict__ out)
{
    const int h = blockIdx.y, b = blockIdx.z;
    const float gh = gamma[h];
    for (int h2 = 0; h2 < h; h2++)
        if (gamma[h2] == gh) return;           // only leaders broadcast

    size_t idx = ((size_t)blockIdx.x * 256 + threadIdx.x) * 4;
    const float4 v = *(const float4*)&out[((size_t)(b*Hh + h)*Ss)*Dd + idx];
    for (int h2 = h + 1; h2 < Hh; h2++) {
        if (gamma[h2] != gh) continue;
        *(float4*)&out[((size_t)(b*Hh + h2)*Ss)*Dd + idx] = v;
    }
}

// ---------------------------------------------------------------------------
extern "C" void kernel_launch(void* const* d_in, const int* in_sizes, int n_in,
                              void* d_out, int out_size)
{
    // metadata order: x, e, p, W_q, W_k, W_v, gamma
    const float* e     = (const float*)d_in[1];
    const float* p     = (const float*)d_in[2];
    const float* Wq    = (const float*)d_in[3];
    const float* Wk    = (const float*)d_in[4];
    const float* Wv    = (const float*)d_in[5];
    const float* gamma = (const float*)d_in[6];
    float* out = (float*)d_out;

    static bool init_done = false;
    static void *q2p = nullptr, *k2p = nullptr;
    if (!init_done) {
        cudaFuncSetAttribute(proj_mma_kernel,
                             cudaFuncAttributeMaxDynamicSharedMemorySize, PROJ_SMEM);
        cudaFuncSetAttribute(fused_attn_kernel,
                             cudaFuncAttributeMaxDynamicSharedMemorySize, FUSED_SMEM);
        cudaGetSymbolAddress(&q2p, g_q2);
        cudaGetSymbolAddress(&k2p, g_k2);
        init_done = true;
    }

    cudaMemsetAsync(q2p, 0, NR * sizeof(float));
    cudaMemsetAsync(k2p, 0, NR * sizeof(float));

    dim3 gz((Ss*Dd)/1024, Hh, Bb);
    zero_kernel<<<gz, 256>>>(gamma, out);

    dim3 gi((NR*Dd)/1024, 2);
    insplit_kernel<<<gi, 256>>>(p, e);

    dim3 gw((Dd/2)*Dd/256, 3);
    wsplit_kernel<<<gw, 256>>>(Wq, Wk, Wv);

    dim3 gproj(NR/128, Dd/64, 3);
    proj_mma_kernel<<<gproj, 256, PROJ_SMEM>>>();

    dim3 gf(16, 16, Bb*Hh);
    fused_attn_kernel<<<gf, 256, FUSED_SMEM>>>(gamma, out);

    dim3 gb((Ss*Dd)/1024, Hh, Bb);
    bcast_kernel<<<gb, 256>>>(gamma, out);
}